// round 10
// baseline (speedup 1.0000x reference)
#include <cuda_runtime.h>
#include <stdint.h>

// ---------------------------------------------------------------------------
// Soft-sphere multi-species pair potential: energy, per-atom energies, forces,
// virial stress. Output: [energy(1) | energies(N) | forces(3N) | stress(9)]
// ---------------------------------------------------------------------------

#define MAX_ATOMS 100352   // N_ATOMS = 100000, padded
#define NS_MAX    16

__device__ float4  g_acc[MAX_ATOMS];    // fx, fy, fz, 0.5*sum(e_pair) per atom
__device__ float4  g_pos4[MAX_ATOMS];   // x, y, z, species(int bits)
__device__ double  g_scal[7];           // energy, sxx, syy, szz, sxy, sxz, syz
__device__ int     g_map64;             // 1 if mapping stored as int64
__device__ int     g_spec64;            // 1 if species stored as int64

// Vector global reduction: one 16B red op on sm_90+.
__device__ __forceinline__ void red_add4(float4* addr, float a, float b,
                                         float c, float d) {
#if defined(__CUDA_ARCH__) && (__CUDA_ARCH__ >= 900)
    asm volatile("red.global.add.v4.f32 [%0], {%1, %2, %3, %4};"
                 :: "l"(addr), "f"(a), "f"(b), "f"(c), "f"(d)
                 : "memory");
#else
    atomicAdd(&addr->x, a);
    atomicAdd(&addr->y, b);
    atomicAdd(&addr->z, c);
    atomicAdd(&addr->w, d);
#endif
}

// ---------------------------------------------------------------------------
// Detect int64 vs int32 storage (one warp; all 128 loads in flight).
// ---------------------------------------------------------------------------
__global__ void detect_kernel(const int* __restrict__ mapw,
                              const int* __restrict__ specw) {
    int t = threadIdx.x;
    int m = mapw[2 * t + 1]  | mapw[2 * (t + 32) + 1];
    int s = specw[2 * t + 1] | specw[2 * (t + 32) + 1];
    unsigned bm = __ballot_sync(0xffffffffu, m != 0);
    unsigned bs = __ballot_sync(0xffffffffu, s != 0);
    if (t == 0) {
        g_map64  = (bm == 0u);
        g_spec64 = (bs == 0u);
    }
}

__global__ void init_zero_kernel(int n) {
    int t = blockIdx.x * blockDim.x + threadIdx.x;
    if (t < n) g_acc[t] = make_float4(0.f, 0.f, 0.f, 0.f);
    if (t < 7) g_scal[t] = 0.0;
}

__global__ void init_pos_kernel(const float* __restrict__ pos,
                                const void*  __restrict__ spec,
                                int n) {
    int t = blockIdx.x * blockDim.x + threadIdx.x;
    if (t < n) {
        int sp;
        if (g_spec64) sp = (int)((const long long*)spec)[t];
        else          sp = ((const int*)spec)[t];
        g_pos4[t] = make_float4(pos[3 * t], pos[3 * t + 1], pos[3 * t + 2],
                                __int_as_float(sp));
    }
}

// ---------------------------------------------------------------------------
// Main pair kernel: 2 pairs per thread per iteration (the R6 shape that
// measured best), with __launch_bounds__(256, 6) to cap registers at ~42
// and lift occupancy from 5 to 6 CTAs/SM.
// ---------------------------------------------------------------------------
__global__ __launch_bounds__(256, 6)
void pair_kernel(const void*  __restrict__ map,
                 const float* __restrict__ shifts,
                 const float* __restrict__ cell,
                 const float* __restrict__ sigm,
                 const float* __restrict__ epsm,
                 const float* __restrict__ alpm,
                 int nPairs, int ns) {
    __shared__ float s_sg2[NS_MAX * NS_MAX];   // sigma^2 (single gate)
    __shared__ float s_isg[NS_MAX * NS_MAX];   // 1/sigma
    __shared__ float s_ea [NS_MAX * NS_MAX];   // 0.5*eps/alpha
    __shared__ float s_es [NS_MAX * NS_MAX];   // eps/sigma
    __shared__ float s_am1[NS_MAX * NS_MAX];   // alpha-1
    __shared__ float s_cell[9];
    __shared__ float s_red[7][8];

    int tid = threadIdx.x;
    for (int q = tid; q < ns * ns; q += blockDim.x) {
        float sg = sigm[q], ep = epsm[q], al = alpm[q];
        s_sg2[q] = sg * sg;
        s_isg[q] = 1.0f / sg;
        s_ea [q] = 0.5f * ep / al;
        s_es [q] = ep / sg;
        s_am1[q] = al - 1.0f;
    }
    if (tid < 9) s_cell[tid] = cell[tid];
    __syncthreads();

    const int m64 = g_map64;
    const long long* map64p = (const long long*)map;
    const int*       map32p = (const int*)map;

    float en = 0.f, sxx = 0.f, syy = 0.f, szz = 0.f,
          sxy = 0.f, sxz = 0.f, syz = 0.f;

    auto process = [&](int i, int j, float s0, float s1, float s2) {
        float4 pi = g_pos4[i];
        float4 pj = g_pos4[j];
        float dx = pj.x - pi.x + s0 * s_cell[0] + s1 * s_cell[3] + s2 * s_cell[6];
        float dy = pj.y - pi.y + s0 * s_cell[1] + s1 * s_cell[4] + s2 * s_cell[7];
        float dz = pj.z - pi.z + s0 * s_cell[2] + s1 * s_cell[5] + s2 * s_cell[8];
        float r2 = dx * dx + dy * dy + dz * dz;
        int q = __float_as_int(pi.w) * ns + __float_as_int(pj.w);
        if (r2 < s_sg2[q]) {
            float rinv = rsqrtf(r2);
            float r    = r2 * rinv;
            float base = 1.0f - r * s_isg[q];
            float pm1  = __powf(base, s_am1[q]);
            float he   = s_ea[q] * pm1 * base;     // 0.5 * e_pair
            float c    = s_es[q] * pm1 * rinv;     // f_pair / r
            float fx = c * dx, fy = c * dy, fz = c * dz;
            en  += he;
            sxx += fx * dx; syy += fy * dy; szz += fz * dz;
            sxy += fx * dy; sxz += fx * dz; syz += fy * dz;
            red_add4(g_acc + i,  fx,  fy,  fz, he);
            red_add4(g_acc + j, -fx, -fy, -fz, he);
        }
    };

    int stride = gridDim.x * blockDim.x;
    if ((nPairs & 1) == 0) {
        int nHalf = nPairs >> 1;
        for (int h = blockIdx.x * blockDim.x + tid; h < nHalf; h += stride) {
            int p = 2 * h;
            int i0, j0, i1, j1;
            if (m64) {
                int4 vi = *(const int4*)(map64p + p);
                int4 vj = *(const int4*)(map64p + nPairs + p);
                i0 = vi.x; i1 = vi.z; j0 = vj.x; j1 = vj.z;
            } else {
                int2 vi = *(const int2*)(map32p + p);
                int2 vj = *(const int2*)(map32p + nPairs + p);
                i0 = vi.x; i1 = vi.y; j0 = vj.x; j1 = vj.y;
            }
            float2 sA = *(const float2*)(shifts + 3 * p);
            float2 sB = *(const float2*)(shifts + 3 * p + 2);
            float2 sC = *(const float2*)(shifts + 3 * p + 4);
            process(i0, j0, sA.x, sA.y, sB.x);
            process(i1, j1, sB.y, sC.x, sC.y);
        }
    } else {
        for (int p = blockIdx.x * blockDim.x + tid; p < nPairs; p += stride) {
            int i, j;
            if (m64) { i = (int)map64p[p]; j = (int)map64p[nPairs + p]; }
            else     { i = map32p[p];      j = map32p[nPairs + p]; }
            process(i, j, shifts[3 * p], shifts[3 * p + 1], shifts[3 * p + 2]);
        }
    }

    // Block reduction of 7 scalars, then one double atomicAdd each per block.
    float v[7] = {en, sxx, syy, szz, sxy, sxz, syz};
    int lane = tid & 31, warp = tid >> 5;
    #pragma unroll
    for (int q = 0; q < 7; q++) {
        float x = v[q];
        #pragma unroll
        for (int o = 16; o > 0; o >>= 1) x += __shfl_down_sync(0xffffffffu, x, o);
        if (lane == 0) s_red[q][warp] = x;
    }
    __syncthreads();
    if (tid < 7) {
        float x = 0.f;
        int nw = (blockDim.x + 31) >> 5;
        for (int w = 0; w < nw; w++) x += s_red[tid][w];
        atomicAdd(&g_scal[tid], (double)x);
    }
}

// ---------------------------------------------------------------------------
// Finalize: coalesced load of g_acc, smem transpose, coalesced stores.
// ---------------------------------------------------------------------------
__global__ __launch_bounds__(256)
void finalize_kernel(float* __restrict__ out,
                     const float* __restrict__ cell, int n) {
    __shared__ float sf[768];
    int t = threadIdx.x;
    int base = blockIdx.x * 256;
    int rem = n - base;
    if (rem > 256) rem = 256;

    if (t < rem) {
        float4 a = g_acc[base + t];
        out[1 + base + t] = a.w;
        sf[3 * t + 0] = a.x;
        sf[3 * t + 1] = a.y;
        sf[3 * t + 2] = a.z;
    }
    __syncthreads();
    int fb = 1 + n + 3 * base;
    int m3 = 3 * rem;
    #pragma unroll
    for (int k = 0; k < 3; k++) {
        int idx = t + k * 256;
        if (idx < m3) out[fb + idx] = sf[idx];
    }

    if (blockIdx.x == 0 && t == 0) {
        out[0] = (float)g_scal[0];
        float a00 = cell[0], a01 = cell[1], a02 = cell[2];
        float a10 = cell[3], a11 = cell[4], a12 = cell[5];
        float a20 = cell[6], a21 = cell[7], a22 = cell[8];
        float det = a00 * (a11 * a22 - a12 * a21)
                  - a01 * (a10 * a22 - a12 * a20)
                  + a02 * (a10 * a21 - a11 * a20);
        double inv_vol = 1.0 / (double)fabsf(det);
        double s[6];
        for (int q = 0; q < 6; q++) s[q] = g_scal[1 + q];
        const int idx[3][3] = {{0, 3, 4}, {3, 1, 5}, {4, 5, 2}};
        for (int a = 0; a < 3; a++)
            for (int b = 0; b < 3; b++)
                out[1 + 4 * n + 3 * a + b] = (float)(-s[idx[a][b]] * inv_vol);
    }
}

// ---------------------------------------------------------------------------
extern "C" void kernel_launch(void* const* d_in, const int* in_sizes, int n_in,
                              void* d_out, int out_size) {
    // metadata order: positions, cell, sigma_matrix, epsilon_matrix,
    //                 alpha_matrix, shifts, mapping, species
    const float* pos    = (const float*)d_in[0];
    const float* cell   = (const float*)d_in[1];
    const float* sigm   = (const float*)d_in[2];
    const float* epsm   = (const float*)d_in[3];
    const float* alpm   = (const float*)d_in[4];
    const float* shifts = (const float*)d_in[5];
    const void*  map    = d_in[6];
    const void*  spec   = d_in[7];

    int n  = in_sizes[0] / 3;   // atoms
    int P  = in_sizes[5] / 3;   // pairs (shifts is [P,3] f32, dtype-unambiguous)
    int m2 = in_sizes[2];
    int ns = 1;
    while (ns * ns < m2) ns++;
    if (ns > NS_MAX) ns = NS_MAX;

    detect_kernel<<<1, 32>>>((const int*)map, (const int*)spec);
    init_zero_kernel<<<(n + 255) / 256, 256>>>(n);
    init_pos_kernel<<<(n + 255) / 256, 256>>>(pos, spec, n);
    pair_kernel<<<2048, 256>>>(map, shifts, cell, sigm, epsm, alpm, P, ns);
    finalize_kernel<<<(n + 255) / 256, 256>>>((float*)d_out, cell, n);
}

// round 12
// speedup vs baseline: 1.3421x; 1.3421x over previous
#include <cuda_runtime.h>
#include <stdint.h>

// ---------------------------------------------------------------------------
// Soft-sphere multi-species pair potential: energy, per-atom energies, forces,
// virial stress. Output: [energy(1) | energies(N) | forces(3N) | stress(9)]
// ---------------------------------------------------------------------------

#define MAX_ATOMS 100352   // N_ATOMS = 100000, padded
#define NS_MAX    16

__device__ float4  g_acc[MAX_ATOMS];    // fx, fy, fz, 0.5*sum(e_pair) per atom
__device__ float4  g_pos4[MAX_ATOMS];   // x, y, z, species(int bits)
__device__ double  g_scal[7];           // energy, sxx, syy, szz, sxy, sxz, syz
__device__ int     g_map64;             // 1 if mapping stored as int64
__device__ int     g_spec64;            // 1 if species stored as int64

// Vector global reduction: one 16B red op on sm_90+.
__device__ __forceinline__ void red_add4(float4* addr, float a, float b,
                                         float c, float d) {
#if defined(__CUDA_ARCH__) && (__CUDA_ARCH__ >= 900)
    asm volatile("red.global.add.v4.f32 [%0], {%1, %2, %3, %4};"
                 :: "l"(addr), "f"(a), "f"(b), "f"(c), "f"(d)
                 : "memory");
#else
    atomicAdd(&addr->x, a);
    atomicAdd(&addr->y, b);
    atomicAdd(&addr->z, c);
    atomicAdd(&addr->w, d);
#endif
}

// ---------------------------------------------------------------------------
// Detect int64 vs int32 storage (one warp; all 128 loads in flight).
// ---------------------------------------------------------------------------
__global__ void detect_kernel(const int* __restrict__ mapw,
                              const int* __restrict__ specw) {
    int t = threadIdx.x;
    int m = mapw[2 * t + 1]  | mapw[2 * (t + 32) + 1];
    int s = specw[2 * t + 1] | specw[2 * (t + 32) + 1];
    unsigned bm = __ballot_sync(0xffffffffu, m != 0);
    unsigned bs = __ballot_sync(0xffffffffu, s != 0);
    if (t == 0) {
        g_map64  = (bm == 0u);
        g_spec64 = (bs == 0u);
    }
}

// ---------------------------------------------------------------------------
// Merged init: zero accumulators + scalars, pack (pos, species) into float4.
// ---------------------------------------------------------------------------
__global__ void init_kernel(const float* __restrict__ pos,
                            const void*  __restrict__ spec,
                            int n) {
    int t = blockIdx.x * blockDim.x + threadIdx.x;
    if (t < n) {
        int sp;
        if (g_spec64) sp = (int)((const long long*)spec)[t];
        else          sp = ((const int*)spec)[t];
        g_pos4[t] = make_float4(pos[3 * t], pos[3 * t + 1], pos[3 * t + 2],
                                __int_as_float(sp));
        g_acc[t]  = make_float4(0.f, 0.f, 0.f, 0.f);
    }
    if (t < 7) g_scal[t] = 0.0;
}

// ---------------------------------------------------------------------------
// Main pair kernel: the R6-measured-best shape (2 pairs/thread, 48 regs,
// no occupancy cap), launched as exactly one resident wave (740 blocks).
// ---------------------------------------------------------------------------
__global__ __launch_bounds__(256)
void pair_kernel(const void*  __restrict__ map,
                 const float* __restrict__ shifts,
                 const float* __restrict__ cell,
                 const float* __restrict__ sigm,
                 const float* __restrict__ epsm,
                 const float* __restrict__ alpm,
                 int nPairs, int ns) {
    __shared__ float s_sg2[NS_MAX * NS_MAX];   // sigma^2 (single gate)
    __shared__ float s_isg[NS_MAX * NS_MAX];   // 1/sigma
    __shared__ float s_ea [NS_MAX * NS_MAX];   // 0.5*eps/alpha
    __shared__ float s_es [NS_MAX * NS_MAX];   // eps/sigma
    __shared__ float s_am1[NS_MAX * NS_MAX];   // alpha-1
    __shared__ float s_cell[9];
    __shared__ float s_red[7][8];

    int tid = threadIdx.x;
    for (int q = tid; q < ns * ns; q += blockDim.x) {
        float sg = sigm[q], ep = epsm[q], al = alpm[q];
        s_sg2[q] = sg * sg;
        s_isg[q] = 1.0f / sg;
        s_ea [q] = 0.5f * ep / al;
        s_es [q] = ep / sg;
        s_am1[q] = al - 1.0f;
    }
    if (tid < 9) s_cell[tid] = cell[tid];
    __syncthreads();

    const int m64 = g_map64;
    const long long* map64p = (const long long*)map;
    const int*       map32p = (const int*)map;
    const float c00 = s_cell[0], c01 = s_cell[1], c02 = s_cell[2];
    const float c10 = s_cell[3], c11 = s_cell[4], c12 = s_cell[5];
    const float c20 = s_cell[6], c21 = s_cell[7], c22 = s_cell[8];

    float en = 0.f, sxx = 0.f, syy = 0.f, szz = 0.f,
          sxy = 0.f, sxz = 0.f, syz = 0.f;

    auto process = [&](int i, int j, float s0, float s1, float s2) {
        float4 pi = __ldg(g_pos4 + i);
        float4 pj = __ldg(g_pos4 + j);
        float dx = pj.x - pi.x + s0 * c00 + s1 * c10 + s2 * c20;
        float dy = pj.y - pi.y + s0 * c01 + s1 * c11 + s2 * c21;
        float dz = pj.z - pi.z + s0 * c02 + s1 * c12 + s2 * c22;
        float r2 = dx * dx + dy * dy + dz * dz;
        int q = __float_as_int(pi.w) * ns + __float_as_int(pj.w);
        if (r2 < s_sg2[q]) {
            float rinv = rsqrtf(r2);
            float r    = r2 * rinv;
            float base = 1.0f - r * s_isg[q];
            float pm1  = __powf(base, s_am1[q]);
            float he   = s_ea[q] * pm1 * base;     // 0.5 * e_pair
            float c    = s_es[q] * pm1 * rinv;     // f_pair / r
            float fx = c * dx, fy = c * dy, fz = c * dz;
            en  += he;
            sxx += fx * dx; syy += fy * dy; szz += fz * dz;
            sxy += fx * dy; sxz += fx * dz; syz += fy * dz;
            red_add4(g_acc + i,  fx,  fy,  fz, he);
            red_add4(g_acc + j, -fx, -fy, -fz, he);
        }
    };

    int stride = gridDim.x * blockDim.x;
    if ((nPairs & 1) == 0) {
        int nHalf = nPairs >> 1;
        for (int h = blockIdx.x * blockDim.x + tid; h < nHalf; h += stride) {
            int p = 2 * h;
            int i0, j0, i1, j1;
            if (m64) {
                int4 vi = *(const int4*)(map64p + p);
                int4 vj = *(const int4*)(map64p + nPairs + p);
                i0 = vi.x; i1 = vi.z; j0 = vj.x; j1 = vj.z;
            } else {
                int2 vi = *(const int2*)(map32p + p);
                int2 vj = *(const int2*)(map32p + nPairs + p);
                i0 = vi.x; i1 = vi.y; j0 = vj.x; j1 = vj.y;
            }
            float2 sA = *(const float2*)(shifts + 3 * p);
            float2 sB = *(const float2*)(shifts + 3 * p + 2);
            float2 sC = *(const float2*)(shifts + 3 * p + 4);
            process(i0, j0, sA.x, sA.y, sB.x);
            process(i1, j1, sB.y, sC.x, sC.y);
        }
    } else {
        for (int p = blockIdx.x * blockDim.x + tid; p < nPairs; p += stride) {
            int i, j;
            if (m64) { i = (int)map64p[p]; j = (int)map64p[nPairs + p]; }
            else     { i = map32p[p];      j = map32p[nPairs + p]; }
            process(i, j, shifts[3 * p], shifts[3 * p + 1], shifts[3 * p + 2]);
        }
    }

    // Block reduction of 7 scalars, then one double atomicAdd each per block.
    float v[7] = {en, sxx, syy, szz, sxy, sxz, syz};
    int lane = tid & 31, warp = tid >> 5;
    #pragma unroll
    for (int q = 0; q < 7; q++) {
        float x = v[q];
        #pragma unroll
        for (int o = 16; o > 0; o >>= 1) x += __shfl_down_sync(0xffffffffu, x, o);
        if (lane == 0) s_red[q][warp] = x;
    }
    __syncthreads();
    if (tid < 7) {
        float x = 0.f;
        int nw = (blockDim.x + 31) >> 5;
        for (int w = 0; w < nw; w++) x += s_red[tid][w];
        atomicAdd(&g_scal[tid], (double)x);
    }
}

// ---------------------------------------------------------------------------
// Finalize: coalesced load of g_acc, smem transpose, coalesced stores.
// ---------------------------------------------------------------------------
__global__ __launch_bounds__(256)
void finalize_kernel(float* __restrict__ out,
                     const float* __restrict__ cell, int n) {
    __shared__ float sf[768];
    int t = threadIdx.x;
    int base = blockIdx.x * 256;
    int rem = n - base;
    if (rem > 256) rem = 256;

    if (t < rem) {
        float4 a = g_acc[base + t];
        out[1 + base + t] = a.w;
        sf[3 * t + 0] = a.x;
        sf[3 * t + 1] = a.y;
        sf[3 * t + 2] = a.z;
    }
    __syncthreads();
    int fb = 1 + n + 3 * base;
    int m3 = 3 * rem;
    #pragma unroll
    for (int k = 0; k < 3; k++) {
        int idx = t + k * 256;
        if (idx < m3) out[fb + idx] = sf[idx];
    }

    if (blockIdx.x == 0 && t == 0) {
        out[0] = (float)g_scal[0];
        float a00 = cell[0], a01 = cell[1], a02 = cell[2];
        float a10 = cell[3], a11 = cell[4], a12 = cell[5];
        float a20 = cell[6], a21 = cell[7], a22 = cell[8];
        float det = a00 * (a11 * a22 - a12 * a21)
                  - a01 * (a10 * a22 - a12 * a20)
                  + a02 * (a10 * a21 - a11 * a20);
        double inv_vol = 1.0 / (double)fabsf(det);
        double s[6];
        for (int q = 0; q < 6; q++) s[q] = g_scal[1 + q];
        const int idx[3][3] = {{0, 3, 4}, {3, 1, 5}, {4, 5, 2}};
        for (int a = 0; a < 3; a++)
            for (int b = 0; b < 3; b++)
                out[1 + 4 * n + 3 * a + b] = (float)(-s[idx[a][b]] * inv_vol);
    }
}

// ---------------------------------------------------------------------------
extern "C" void kernel_launch(void* const* d_in, const int* in_sizes, int n_in,
                              void* d_out, int out_size) {
    // metadata order: positions, cell, sigma_matrix, epsilon_matrix,
    //                 alpha_matrix, shifts, mapping, species
    const float* pos    = (const float*)d_in[0];
    const float* cell   = (const float*)d_in[1];
    const float* sigm   = (const float*)d_in[2];
    const float* epsm   = (const float*)d_in[3];
    const float* alpm   = (const float*)d_in[4];
    const float* shifts = (const float*)d_in[5];
    const void*  map    = d_in[6];
    const void*  spec   = d_in[7];

    int n  = in_sizes[0] / 3;   // atoms
    int P  = in_sizes[5] / 3;   // pairs (shifts is [P,3] f32, dtype-unambiguous)
    int m2 = in_sizes[2];
    int ns = 1;
    while (ns * ns < m2) ns++;
    if (ns > NS_MAX) ns = NS_MAX;

    detect_kernel<<<1, 32>>>((const int*)map, (const int*)spec);
    init_kernel<<<(n + 255) / 256, 256>>>(pos, spec, n);
    // 740 = 148 SMs x 5 resident CTAs at 48 regs: exactly one wave.
    pair_kernel<<<740, 256>>>(map, shifts, cell, sigm, epsm, alpm, P, ns);
    finalize_kernel<<<(n + 255) / 256, 256>>>((float*)d_out, cell, n);
}

// round 14
// speedup vs baseline: 1.3551x; 1.0097x over previous
#include <cuda_runtime.h>
#include <stdint.h>

// ---------------------------------------------------------------------------
// Soft-sphere multi-species pair potential: energy, per-atom energies, forces,
// virial stress. Output: [energy(1) | energies(N) | forces(3N) | stress(9)]
// ---------------------------------------------------------------------------

#define MAX_ATOMS 100352   // N_ATOMS = 100000, padded
#define NS_MAX    16

__device__ float4  g_acc[MAX_ATOMS];    // fx, fy, fz, 0.5*sum(e_pair) per atom
__device__ float4  g_pos4[MAX_ATOMS];   // x, y, z, species(int bits)
__device__ double  g_scal[7];           // energy, sxx, syy, szz, sxy, sxz, syz

// Vector global reduction: one 16B red op on sm_90+.
__device__ __forceinline__ void red_add4(float4* addr, float a, float b,
                                         float c, float d) {
#if defined(__CUDA_ARCH__) && (__CUDA_ARCH__ >= 900)
    asm volatile("red.global.add.v4.f32 [%0], {%1, %2, %3, %4};"
                 :: "l"(addr), "f"(a), "f"(b), "f"(c), "f"(d)
                 : "memory");
#else
    atomicAdd(&addr->x, a);
    atomicAdd(&addr->y, b);
    atomicAdd(&addr->z, c);
    atomicAdd(&addr->w, d);
#endif
}

// In-kernel int64-vs-int32 detection: warp 0 reads 128 odd 32-bit words
// (all-zero iff the array is int64 with values < 2^31; false-positive
// probability ~8^-64). Requires the array to hold >= 128 32-bit words.
// All loads L2-resident after the first block. Result -> *out (shared).
__device__ __forceinline__ void detect64_warp0(const void* arr, int tid,
                                               int* out) {
    if (tid < 32) {
        const int* w = (const int*)arr;
        int x = w[2 * tid + 1] | w[2 * (tid + 32) + 1];
        unsigned b = __ballot_sync(0xffffffffu, x != 0);
        if (tid == 0) *out = (b == 0u);
    }
}

// ---------------------------------------------------------------------------
// Init: detect species dtype (warp 0), stage pos through smem (coalesced),
// pack (pos, species) into float4, zero accumulators + scalars.
// ---------------------------------------------------------------------------
__global__ __launch_bounds__(256)
void init_kernel(const float* __restrict__ pos,
                 const void*  __restrict__ spec,
                 int n) {
    __shared__ float sp[768];
    __shared__ int s_spec64;
    int t = threadIdx.x;
    int base = blockIdx.x * 256;

    detect64_warp0(spec, t, &s_spec64);

    int rem = n - base;
    if (rem > 256) rem = 256;
    int m3 = 3 * rem;
    #pragma unroll
    for (int k = 0; k < 3; k++) {
        int idx = t + k * 256;
        if (idx < m3) sp[idx] = pos[3 * base + idx];   // coalesced loads
    }
    __syncthreads();

    if (t < rem) {
        int a = base + t;
        int spv;
        if (s_spec64) spv = (int)((const long long*)spec)[a];
        else          spv = ((const int*)spec)[a];
        g_pos4[a] = make_float4(sp[3 * t], sp[3 * t + 1], sp[3 * t + 2],
                                __int_as_float(spv));
        g_acc[a]  = make_float4(0.f, 0.f, 0.f, 0.f);
    }
    if (blockIdx.x == 0 && t < 7) g_scal[t] = 0.0;
}

// ---------------------------------------------------------------------------
// Main pair kernel: R6/R12-measured-best shape (2 pairs/thread, 48 regs),
// one resident wave (740 blocks). Mapping dtype detected in-kernel.
// ---------------------------------------------------------------------------
__global__ __launch_bounds__(256)
void pair_kernel(const void*  __restrict__ map,
                 const float* __restrict__ shifts,
                 const float* __restrict__ cell,
                 const float* __restrict__ sigm,
                 const float* __restrict__ epsm,
                 const float* __restrict__ alpm,
                 int nPairs, int ns) {
    __shared__ float s_sg2[NS_MAX * NS_MAX];   // sigma^2 (single gate)
    __shared__ float s_isg[NS_MAX * NS_MAX];   // 1/sigma
    __shared__ float s_ea [NS_MAX * NS_MAX];   // 0.5*eps/alpha
    __shared__ float s_es [NS_MAX * NS_MAX];   // eps/sigma
    __shared__ float s_am1[NS_MAX * NS_MAX];   // alpha-1
    __shared__ float s_cell[9];
    __shared__ float s_red[7][8];
    __shared__ int   s_m64;

    int tid = threadIdx.x;
    detect64_warp0(map, tid, &s_m64);
    for (int q = tid; q < ns * ns; q += blockDim.x) {
        float sg = sigm[q], ep = epsm[q], al = alpm[q];
        s_sg2[q] = sg * sg;
        s_isg[q] = 1.0f / sg;
        s_ea [q] = 0.5f * ep / al;
        s_es [q] = ep / sg;
        s_am1[q] = al - 1.0f;
    }
    if (tid < 9) s_cell[tid] = cell[tid];
    __syncthreads();

    const int m64 = s_m64;
    const long long* map64p = (const long long*)map;
    const int*       map32p = (const int*)map;
    const float c00 = s_cell[0], c01 = s_cell[1], c02 = s_cell[2];
    const float c10 = s_cell[3], c11 = s_cell[4], c12 = s_cell[5];
    const float c20 = s_cell[6], c21 = s_cell[7], c22 = s_cell[8];

    float en = 0.f, sxx = 0.f, syy = 0.f, szz = 0.f,
          sxy = 0.f, sxz = 0.f, syz = 0.f;

    auto process = [&](int i, int j, float s0, float s1, float s2) {
        float4 pi = __ldg(g_pos4 + i);
        float4 pj = __ldg(g_pos4 + j);
        float dx = pj.x - pi.x + s0 * c00 + s1 * c10 + s2 * c20;
        float dy = pj.y - pi.y + s0 * c01 + s1 * c11 + s2 * c21;
        float dz = pj.z - pi.z + s0 * c02 + s1 * c12 + s2 * c22;
        float r2 = dx * dx + dy * dy + dz * dz;
        int q = __float_as_int(pi.w) * ns + __float_as_int(pj.w);
        if (r2 < s_sg2[q]) {
            float rinv = rsqrtf(r2);
            float r    = r2 * rinv;
            float base = 1.0f - r * s_isg[q];
            float pm1  = __powf(base, s_am1[q]);
            float he   = s_ea[q] * pm1 * base;     // 0.5 * e_pair
            float c    = s_es[q] * pm1 * rinv;     // f_pair / r
            float fx = c * dx, fy = c * dy, fz = c * dz;
            en  += he;
            sxx += fx * dx; syy += fy * dy; szz += fz * dz;
            sxy += fx * dy; sxz += fx * dz; syz += fy * dz;
            red_add4(g_acc + i,  fx,  fy,  fz, he);
            red_add4(g_acc + j, -fx, -fy, -fz, he);
        }
    };

    int stride = gridDim.x * blockDim.x;
    if ((nPairs & 1) == 0) {
        int nHalf = nPairs >> 1;
        for (int h = blockIdx.x * blockDim.x + tid; h < nHalf; h += stride) {
            int p = 2 * h;
            int i0, j0, i1, j1;
            if (m64) {
                int4 vi = *(const int4*)(map64p + p);
                int4 vj = *(const int4*)(map64p + nPairs + p);
                i0 = vi.x; i1 = vi.z; j0 = vj.x; j1 = vj.z;
            } else {
                int2 vi = *(const int2*)(map32p + p);
                int2 vj = *(const int2*)(map32p + nPairs + p);
                i0 = vi.x; i1 = vi.y; j0 = vj.x; j1 = vj.y;
            }
            float2 sA = *(const float2*)(shifts + 3 * p);
            float2 sB = *(const float2*)(shifts + 3 * p + 2);
            float2 sC = *(const float2*)(shifts + 3 * p + 4);
            process(i0, j0, sA.x, sA.y, sB.x);
            process(i1, j1, sB.y, sC.x, sC.y);
        }
    } else {
        for (int p = blockIdx.x * blockDim.x + tid; p < nPairs; p += stride) {
            int i, j;
            if (m64) { i = (int)map64p[p]; j = (int)map64p[nPairs + p]; }
            else     { i = map32p[p];      j = map32p[nPairs + p]; }
            process(i, j, shifts[3 * p], shifts[3 * p + 1], shifts[3 * p + 2]);
        }
    }

    // Block reduction of 7 scalars, then one double atomicAdd each per block.
    float v[7] = {en, sxx, syy, szz, sxy, sxz, syz};
    int lane = tid & 31, warp = tid >> 5;
    #pragma unroll
    for (int q = 0; q < 7; q++) {
        float x = v[q];
        #pragma unroll
        for (int o = 16; o > 0; o >>= 1) x += __shfl_down_sync(0xffffffffu, x, o);
        if (lane == 0) s_red[q][warp] = x;
    }
    __syncthreads();
    if (tid < 7) {
        float x = 0.f;
        int nw = (blockDim.x + 31) >> 5;
        for (int w = 0; w < nw; w++) x += s_red[tid][w];
        atomicAdd(&g_scal[tid], (double)x);
    }
}

// ---------------------------------------------------------------------------
// Finalize: coalesced load of g_acc, smem transpose, coalesced stores.
// ---------------------------------------------------------------------------
__global__ __launch_bounds__(256)
void finalize_kernel(float* __restrict__ out,
                     const float* __restrict__ cell, int n) {
    __shared__ float sf[768];
    int t = threadIdx.x;
    int base = blockIdx.x * 256;
    int rem = n - base;
    if (rem > 256) rem = 256;

    if (t < rem) {
        float4 a = g_acc[base + t];
        out[1 + base + t] = a.w;
        sf[3 * t + 0] = a.x;
        sf[3 * t + 1] = a.y;
        sf[3 * t + 2] = a.z;
    }
    __syncthreads();
    int fb = 1 + n + 3 * base;
    int m3 = 3 * rem;
    #pragma unroll
    for (int k = 0; k < 3; k++) {
        int idx = t + k * 256;
        if (idx < m3) out[fb + idx] = sf[idx];
    }

    if (blockIdx.x == 0 && t == 0) {
        out[0] = (float)g_scal[0];
        float a00 = cell[0], a01 = cell[1], a02 = cell[2];
        float a10 = cell[3], a11 = cell[4], a12 = cell[5];
        float a20 = cell[6], a21 = cell[7], a22 = cell[8];
        float det = a00 * (a11 * a22 - a12 * a21)
                  - a01 * (a10 * a22 - a12 * a20)
                  + a02 * (a10 * a21 - a11 * a20);
        double inv_vol = 1.0 / (double)fabsf(det);
        double s[6];
        for (int q = 0; q < 6; q++) s[q] = g_scal[1 + q];
        const int idx[3][3] = {{0, 3, 4}, {3, 1, 5}, {4, 5, 2}};
        for (int a = 0; a < 3; a++)
            for (int b = 0; b < 3; b++)
                out[1 + 4 * n + 3 * a + b] = (float)(-s[idx[a][b]] * inv_vol);
    }
}

// ---------------------------------------------------------------------------
extern "C" void kernel_launch(void* const* d_in, const int* in_sizes, int n_in,
                              void* d_out, int out_size) {
    // metadata order: positions, cell, sigma_matrix, epsilon_matrix,
    //                 alpha_matrix, shifts, mapping, species
    const float* pos    = (const float*)d_in[0];
    const float* cell   = (const float*)d_in[1];
    const float* sigm   = (const float*)d_in[2];
    const float* epsm   = (const float*)d_in[3];
    const float* alpm   = (const float*)d_in[4];
    const float* shifts = (const float*)d_in[5];
    const void*  map    = d_in[6];
    const void*  spec   = d_in[7];

    int n  = in_sizes[0] / 3;   // atoms
    int P  = in_sizes[5] / 3;   // pairs (shifts is [P,3] f32, dtype-unambiguous)
    int m2 = in_sizes[2];
    int ns = 1;
    while (ns * ns < m2) ns++;
    if (ns > NS_MAX) ns = NS_MAX;

    init_kernel<<<(n + 255) / 256, 256>>>(pos, spec, n);
    // 740 = 148 SMs x 5 resident CTAs at 48 regs: exactly one wave.
    pair_kernel<<<740, 256>>>(map, shifts, cell, sigm, epsm, alpm, P, ns);
    finalize_kernel<<<(n + 255) / 256, 256>>>((float*)d_out, cell, n);
}